// round 6
// baseline (speedup 1.0000x reference)
#include <cuda_runtime.h>
#include <cstdint>

// ---------------------------------------------------------------------------
// KeyedGRU  (B=64, T=2048, I=H=256, KB=4, KL=16)  -- all fp32
// A: gi GEMM (131136 x 768 x 256), 128x128 tile, FFMA2, pre-duplicated A tile,
//    double-buffered SMEM.
// B: 16-step key GRU scan, one 4-CTA cluster (validated).
// C: 2048-step main GRU scan, 32 clusters x 4 CTAs, weights in registers,
//    per-step sync via st.async + mbarrier complete_tx (acquire.cluster wait).
//    R5 bug fixed: tid0's arm of the next-step barrier is now ordered before
//    ANY thread's ships via __syncthreads (previously remote complete_tx could
//    reach an unarmed barrier -> phase corruption -> sporadic stale partials).
// ---------------------------------------------------------------------------

#define T_STEPS 2048
#define BATCH   64
#define HID     256
#define ROWS_MAIN (T_STEPS * BATCH)
#define ROWS_ALL  (ROWS_MAIN + 64)
#define CSIZE 4
#define RPC   192
#define WS    260

__device__ float g_gi[(size_t)ROWS_ALL * 768];
__device__ float g_gates[16 * HID];

typedef unsigned long long ull;

// ---------------- helpers ----------------
__device__ __forceinline__ uint32_t smem_u32(const void* p) {
    uint32_t a;
    asm("{ .reg .u64 t; cvta.to.shared.u64 t, %1; cvt.u32.u64 %0, t; }"
        : "=r"(a) : "l"(p));
    return a;
}
__device__ __forceinline__ void st_cluster_f32(uint32_t laddr, uint32_t rank, float v) {
    uint32_t ra;
    asm volatile("mapa.shared::cluster.u32 %0, %1, %2;" : "=r"(ra) : "r"(laddr), "r"(rank));
    asm volatile("st.shared::cluster.f32 [%0], %1;" :: "r"(ra), "f"(v) : "memory");
}
__device__ __forceinline__ uint32_t mapa_addr(uint32_t laddr, uint32_t rank) {
    uint32_t ra;
    asm("mapa.shared::cluster.u32 %0, %1, %2;" : "=r"(ra) : "r"(laddr), "r"(rank));
    return ra;
}
// store 2 floats to remote SMEM + complete_tx (8 bytes) on remote mbarrier
__device__ __forceinline__ void st_async_2f(uint32_t ra, float a, float b, uint32_t rbar) {
    asm volatile("{ .reg .b64 d; mov.b64 d, {%1, %2};\n\t"
                 "st.async.shared::cluster.mbarrier::complete_tx::bytes.b64 [%0], d, [%3]; }"
                 :: "r"(ra), "f"(a), "f"(b), "r"(rbar) : "memory");
}
__device__ __forceinline__ void mbar_init(uint32_t a, uint32_t cnt) {
    asm volatile("mbarrier.init.shared.b64 [%0], %1;" :: "r"(a), "r"(cnt) : "memory");
}
__device__ __forceinline__ void mbar_arrive_expect(uint32_t a, uint32_t tx) {
    asm volatile("mbarrier.arrive.expect_tx.shared.b64 _, [%0], %1;"
                 :: "r"(a), "r"(tx) : "memory");
}
// CLUSTER-scope acquire: pairs with remote CTAs' st.async complete_tx releases.
__device__ __forceinline__ void mbar_wait_parity(uint32_t mbar, uint32_t parity) {
    uint32_t done;
    asm volatile("{\n\t.reg .pred p;\n\t"
                 "mbarrier.try_wait.parity.acquire.cluster.shared::cta.b64 p, [%1], %2;\n\t"
                 "selp.b32 %0, 1, 0, p;\n\t}"
                 : "=r"(done) : "r"(mbar), "r"(parity) : "memory");
    if (!done) {
        asm volatile("{\n\t.reg .pred P1;\n\t"
                     "WAIT_LOOP_%=:\n\t"
                     "mbarrier.try_wait.parity.acquire.cluster.shared::cta.b64 P1, [%0], %1, 0x989680;\n\t"
                     "@P1 bra.uni WAIT_DONE_%=;\n\t"
                     "bra.uni WAIT_LOOP_%=;\n\t"
                     "WAIT_DONE_%=:\n\t}"
                     :: "r"(mbar), "r"(parity) : "memory");
    }
}
__device__ __forceinline__ void cluster_sync_() {
    asm volatile("barrier.cluster.arrive.aligned;" ::: "memory");
    asm volatile("barrier.cluster.wait.aligned;" ::: "memory");
}
__device__ __forceinline__ uint32_t ctarank() {
    uint32_t r; asm("mov.u32 %0, %%cluster_ctarank;" : "=r"(r)); return r;
}
__device__ __forceinline__ void fma2(ull& c, ull a, ull b) {
    asm("fma.rn.f32x2 %0, %1, %2, %0;" : "+l"(c) : "l"(a), "l"(b));
}
__device__ __forceinline__ void unpk(ull v, float& x, float& y) {
    asm("mov.b64 {%0, %1}, %2;" : "=f"(x), "=f"(y) : "l"(v));
}
__device__ __forceinline__ float sigm_(float x)  { return 1.0f / (1.0f + __expf(-x)); }
__device__ __forceinline__ float tanh_(float x)  { return 1.0f - __fdividef(2.0f, __expf(2.0f * x) + 1.0f); }
__device__ __forceinline__ float sigmoidf_(float x) { return 1.0f / (1.0f + expf(-x)); }

// ---------------------------------------------------------------------------
// Kernel A: 128x128 tile GEMM, FFMA2, pre-duplicated A tile, double-buffered.
// grid (6, 1025), block 256, dynamic smem 100KB, 2 CTAs/SM.
// ---------------------------------------------------------------------------
#define AR 268   // As2 row stride (floats)
#define BR 132

__global__ void __launch_bounds__(256, 2) kA(const float* __restrict__ x,
                                             const float* __restrict__ wmk,
                                             const float* __restrict__ wih,
                                             const float* __restrict__ bih)
{
    extern __shared__ __align__(16) float smA[];
    float (*As2)[32][AR] = (float (*)[32][AR])smA;                  // [2][32][268]
    float (*Bs)[32][BR]  = (float (*)[32][BR])(smA + 2 * 32 * AR);  // [2][32][132]

    const int tid = threadIdx.x;
    const int nt = blockIdx.x;       // 0..5
    const int rt = blockIdx.y;       // 0..1024
    const int tx = tid & 15, ty = tid >> 4;
    const int m_base = rt * 128, n_base = nt * 128;

    ull acc[8][4];
    #pragma unroll
    for (int i = 0; i < 8; ++i)
        #pragma unroll
        for (int j = 0; j < 4; ++j) acc[i][j] = 0ull;

    float4 ra[4], rb[4];

    auto load_regs = [&](int kc) {
        const int kb = kc * 32;
        #pragma unroll
        for (int q = 0; q < 4; ++q) {
            int v = tid + q * 256;
            int m = v >> 3;
            int k4 = (v & 7) << 2;
            int row = m_base + m;
            if (row < ROWS_MAIN) {
                int t = row >> 6, b = row & 63;
                ra[q] = *(const float4*)&x[((size_t)b * T_STEPS + t) * 256 + kb + k4];
            } else if (row < ROWS_ALL) {
                int r2 = row - ROWS_MAIN;
                int l = r2 >> 2, kbk = r2 & 3;
                ra[q] = *(const float4*)&wmk[((size_t)kbk * 16 + l) * 256 + kb + k4];
            } else {
                ra[q] = make_float4(0.f, 0.f, 0.f, 0.f);
            }
            rb[q] = *(const float4*)&wih[(size_t)(n_base + m) * 256 + kb + k4];
        }
    };

    auto store_stage = [&](int buf) {
        #pragma unroll
        for (int q = 0; q < 4; ++q) {
            int v = tid + q * 256;
            int m = v >> 3;
            int k4 = (v & 7) << 2;
            const float* av = &ra[q].x;
            const float* bv = &rb[q].x;
            #pragma unroll
            for (int j = 0; j < 4; ++j) {
                *(float2*)&As2[buf][k4 + j][2 * m] = make_float2(av[j], av[j]);
                Bs[buf][k4 + j][m] = bv[j];
            }
        }
    };

    load_regs(0);
    store_stage(0);
    __syncthreads();

    for (int kc = 0; kc < 8; ++kc) {
        if (kc < 7) load_regs(kc + 1);
        const int buf = kc & 1;
        #pragma unroll 8
        for (int k = 0; k < 32; ++k) {
            ulonglong2 a0 = *(const ulonglong2*)&As2[buf][k][ty * 16 + 0];
            ulonglong2 a1 = *(const ulonglong2*)&As2[buf][k][ty * 16 + 4];
            ulonglong2 a2 = *(const ulonglong2*)&As2[buf][k][ty * 16 + 8];
            ulonglong2 a3 = *(const ulonglong2*)&As2[buf][k][ty * 16 + 12];
            ulonglong2 b0 = *(const ulonglong2*)&Bs[buf][k][tx * 4];
            ulonglong2 b1 = *(const ulonglong2*)&Bs[buf][k][64 + tx * 4];
            ull ad[8] = {a0.x, a0.y, a1.x, a1.y, a2.x, a2.y, a3.x, a3.y};
            #pragma unroll
            for (int i = 0; i < 8; ++i) {
                fma2(acc[i][0], ad[i], b0.x);
                fma2(acc[i][1], ad[i], b0.y);
                fma2(acc[i][2], ad[i], b1.x);
                fma2(acc[i][3], ad[i], b1.y);
            }
        }
        if (kc < 7) {
            store_stage((kc + 1) & 1);
            __syncthreads();
        }
    }

    float4 bs0 = *(const float4*)&bih[n_base + tx * 4];
    float4 bs1 = *(const float4*)&bih[n_base + 64 + tx * 4];
    #pragma unroll
    for (int i = 0; i < 8; ++i) {
        int row = m_base + ty * 8 + i;
        if (row >= ROWS_ALL) break;
        float f0, f1, f2, f3;
        unpk(acc[i][0], f0, f1); unpk(acc[i][1], f2, f3);
        float4 o0 = make_float4(f0 + bs0.x, f1 + bs0.y, f2 + bs0.z, f3 + bs0.w);
        *(float4*)&g_gi[(size_t)row * 768 + n_base + tx * 4] = o0;
        unpk(acc[i][2], f0, f1); unpk(acc[i][3], f2, f3);
        float4 o1 = make_float4(f0 + bs1.x, f1 + bs1.y, f2 + bs1.z, f3 + bs1.w);
        *(float4*)&g_gi[(size_t)row * 768 + n_base + 64 + tx * 4] = o1;
    }
}

// ---------------------------------------------------------------------------
// Kernel B: key scan (16 steps, KB=4) -- unchanged (validated, ~25us).
// ---------------------------------------------------------------------------
__global__ void __launch_bounds__(256, 1) __cluster_dims__(CSIZE, 1, 1)
kB(const float* __restrict__ whh, const float* __restrict__ bhh)
{
    extern __shared__ __align__(16) float sm[];
    float* ws   = sm;
    float* hsh  = ws + RPC * WS;
    float* ghx  = hsh + 4 * HID;
    float* rbuf = ghx + 3 * 4 * 64;

    const int tid = threadIdx.x;
    const uint32_t rank = ctarank();

    for (int i = tid; i < RPC * 64; i += 256) {
        int r = i >> 6;
        int k4 = (i & 63) << 2;
        *(float4*)&ws[r * WS + k4] =
            *(const float4*)&whh[((size_t)(rank * RPC + r)) * 256 + k4];
    }
    for (int i = tid; i < 4 * HID; i += 256) hsh[i] = 0.0f;

    const uint32_t hsh_a = smem_u32(hsh);
    const uint32_t ghx_a = smem_u32(ghx);
    cluster_sync_();

    const int hl = tid & 63;
    const int bb = tid >> 6;
    const int hg = (int)rank * 64 + hl;

    for (int t = 0; t < 16; ++t) {
        float ir, ii, inn;
        {
            size_t row = (size_t)(ROWS_MAIN + t * 4 + bb);
            const float* gp = &g_gi[row * 768];
            ir = gp[hg]; ii = gp[256 + hg]; inn = gp[512 + hg];
        }
        if (tid < RPC) {
            const int rg = (int)rank * RPC + tid;
            float acc[4];
            const float bv = bhh[rg];
            #pragma unroll
            for (int b = 0; b < 4; ++b) acc[b] = bv;
            const float* wr = &ws[tid * WS];
            #pragma unroll 4
            for (int k = 0; k < 256; k += 4) {
                float4 w = *(const float4*)&wr[k];
                #pragma unroll
                for (int b = 0; b < 4; ++b) {
                    float4 h4 = *(const float4*)&hsh[b * HID + k];
                    acc[b] += w.x * h4.x + w.y * h4.y + w.z * h4.z + w.w * h4.w;
                }
            }
            const int chunk = rg >> 8;
            const int hv = rg & 255;
            const uint32_t owner = (uint32_t)(hv >> 6);
            const int hvl = hv & 63;
            #pragma unroll
            for (int b = 0; b < 4; ++b) {
                uint32_t addr = ghx_a + (uint32_t)(((chunk * 4 + b) * 64 + hvl) * 4);
                st_cluster_f32(addr, owner, acc[b]);
            }
        }
        cluster_sync_();
        {
            float hr = ghx[(0 * 4 + bb) * 64 + hl];
            float hi = ghx[(1 * 4 + bb) * 64 + hl];
            float hn = ghx[(2 * 4 + bb) * 64 + hl];
            float r = sigmoidf_(ir + hr);
            float z = sigmoidf_(ii + hi);
            float n = tanhf(inn + r * hn);
            float hold = hsh[bb * HID + hg];
            float hy = n + z * (hold - n);
            rbuf[bb * 64 + hl] = r;
            uint32_t addr = hsh_a + (uint32_t)((bb * HID + hg) * 4);
            #pragma unroll
            for (uint32_t rk = 0; rk < CSIZE; ++rk)
                st_cluster_f32(addr, rk, hy);
        }
        __syncthreads();
        if (tid < 64) {
            float s = 0.f;
            #pragma unroll
            for (int b = 0; b < 4; ++b) s += rbuf[b * 64 + tid];
            g_gates[t * 256 + (int)rank * 64 + tid] = s * 0.25f;
        }
        cluster_sync_();
    }
}

// ---------------------------------------------------------------------------
// Kernel C: main scan, k-partitioned, weights in registers.
// Per-step: arm next barrier (tid0) -> __syncthreads -> ship partials via
// st.async/complete_tx -> wait (acquire.cluster) -> epilogue -> __syncthreads.
// The sync between arm and ship guarantees no complete_tx can reach an
// unarmed barrier (remote ships for step t+1 are gated on OUR step-t ships,
// which now all happen after the arm of t+1).
// ---------------------------------------------------------------------------
#define TXB 6144u   // bytes per step per CTA: 4 src * 3 gates * 64 hl * 2b * 4B

__global__ void __launch_bounds__(256, 1) __cluster_dims__(CSIZE, 1, 1)
kC(const float* __restrict__ whh, const float* __restrict__ bhh,
   float* __restrict__ out)
{
    __shared__ __align__(16) float part[2][4][3][64][2];   // 12 KB
    __shared__ __align__(16) float hp[2][64];
    __shared__ __align__(8) unsigned long long mbar[2];

    const int tid = threadIdx.x;
    const uint32_t rank = ctarank();
    const int cl = blockIdx.x >> 2;

    // weights in registers: wp[gate][kpair]
    ull wp[3][32];
    {
        const float* wb = whh + (size_t)rank * 64;
        #pragma unroll
        for (int j = 0; j < 3; ++j) {
            const float* wr = wb + (size_t)(j * 256 + tid) * 256;
            #pragma unroll
            for (int kk = 0; kk < 64; kk += 4) {
                ulonglong2 v = *(const ulonglong2*)&wr[kk];
                wp[j][kk / 2] = v.x;
                wp[j][kk / 2 + 1] = v.y;
            }
        }
    }

    if (tid < 128) hp[tid >> 6][tid & 63] = 0.0f;

    const uint32_t mb_a = smem_u32(&mbar[0]);
    if (tid == 0) {
        mbar_init(mb_a, 1);
        mbar_init(mb_a + 8, 1);
        mbar_arrive_expect(mb_a, TXB);      // arm step 0 (ordered by cluster_sync)
    }

    const uint32_t owner = (uint32_t)(tid >> 6);
    const int hvl = tid & 63;
    const uint32_t part_a = smem_u32(&part[0][0][0][0][0]);
    const uint32_t loff = (uint32_t)((rank * 384 + hvl * 2) * 4); // part[0][rank][0][hvl][0]
    const uint32_t ra_base = mapa_addr(part_a + loff, owner);
    const uint32_t rbar0 = mapa_addr(mb_a, owner);
    const uint32_t rbar1 = mapa_addr(mb_a + 8, owner);

    const int e_b = tid >> 6;
    const int e_hl = tid & 63;
    const int e_hg = (int)rank * 64 + e_hl;
    float bh_r = 0.f, bh_i = 0.f, bh_n = 0.f;
    if (tid < 128) {
        bh_r = bhh[e_hg];
        bh_i = bhh[256 + e_hg];
        bh_n = bhh[512 + e_hg];
    }
    const int b_glob = cl * 2 + e_b;

    cluster_sync_();   // all CTAs: barrier 0 armed, hp zeroed, weights loaded

    for (int t = 0; t < T_STEPS; ++t) {
        // prefetch gi + gate
        float ir = 0.f, ii = 0.f, inn = 0.f, gg = 1.f;
        if (tid < 128) {
            const float* gp = &g_gi[((size_t)t * BATCH + b_glob) * 768];
            ir  = gp[e_hg];
            ii  = gp[256 + e_hg];
            inn = gp[512 + e_hg];
            if (t < 16) gg = g_gates[t * 256 + e_hg];
        }

        // partial gh over local k-slice
        ull a00 = 0, a01 = 0, a10 = 0, a11 = 0, a20 = 0, a21 = 0;
        #pragma unroll
        for (int kk = 0; kk < 64; kk += 4) {
            ulonglong2 h0 = *(const ulonglong2*)&hp[0][kk];
            ulonglong2 h1 = *(const ulonglong2*)&hp[1][kk];
            ull w0a = wp[0][kk / 2], w0b = wp[0][kk / 2 + 1];
            ull w1a = wp[1][kk / 2], w1b = wp[1][kk / 2 + 1];
            ull w2a = wp[2][kk / 2], w2b = wp[2][kk / 2 + 1];
            fma2(a00, w0a, h0.x); fma2(a00, w0b, h0.y);
            fma2(a01, w0a, h1.x); fma2(a01, w0b, h1.y);
            fma2(a10, w1a, h0.x); fma2(a10, w1b, h0.y);
            fma2(a11, w1a, h1.x); fma2(a11, w1b, h1.y);
            fma2(a20, w2a, h0.x); fma2(a20, w2b, h0.y);
            fma2(a21, w2a, h1.x); fma2(a21, w2b, h1.y);
        }

        // arm NEXT step's barrier, then ORDER the arm before any ship
        if (tid == 0)
            mbar_arrive_expect(mb_a + 8u * ((t + 1) & 1), TXB);
        __syncthreads();

        // ship partials to owner with complete_tx
        {
            const uint32_t pbase = ra_base + (uint32_t)((t & 1) * 6144);
            const uint32_t rb = (t & 1) ? rbar1 : rbar0;
            float x0, y0, x1, y1;
            unpk(a00, x0, y0); unpk(a01, x1, y1);
            st_async_2f(pbase + 0 * 512, x0 + y0, x1 + y1, rb);
            unpk(a10, x0, y0); unpk(a11, x1, y1);
            st_async_2f(pbase + 1 * 512, x0 + y0, x1 + y1, rb);
            unpk(a20, x0, y0); unpk(a21, x1, y1);
            st_async_2f(pbase + 2 * 512, x0 + y0, x1 + y1, rb);
        }

        // wait for all 4 CTAs' partials (cluster-scope acquire)
        mbar_wait_parity(mb_a + 8u * (t & 1), (uint32_t)((t >> 1) & 1));

        // epilogue
        if (tid < 128) {
            const int p = t & 1;
            float s_r = bh_r, s_i = bh_i, s_n = bh_n;
            #pragma unroll
            for (int src = 0; src < 4; ++src) {
                s_r += part[p][src][0][e_hl][e_b];
                s_i += part[p][src][1][e_hl][e_b];
                s_n += part[p][src][2][e_hl][e_b];
            }
            float r = sigm_(ir + s_r);
            float z = sigm_(ii + s_i);
            float n = tanh_(inn + r * s_n);
            float hold = hp[e_b][e_hl];
            float hy = n + z * (hold - n);
            out[((size_t)t * BATCH + b_glob) * HID + e_hg] = hy;
            hp[e_b][e_hl] = hy * gg;
        }
        __syncthreads();
    }
}

// ---------------------------------------------------------------------------
extern "C" void kernel_launch(void* const* d_in, const int* in_sizes, int n_in,
                              void* d_out, int out_size)
{
    const float* x   = (const float*)d_in[0];
    const float* wmk = (const float*)d_in[1];
    const float* wih = (const float*)d_in[2];
    const float* whh = (const float*)d_in[3];
    const float* bih = (const float*)d_in[4];
    const float* bhh = (const float*)d_in[5];
    float* out = (float*)d_out;

    constexpr int SMEM_A   = (2 * 32 * AR + 2 * 32 * BR) * 4;   // 102,400 B
    constexpr int SMEM_KEY = (RPC * WS + 4 * HID + 3 * 4 * 64 + 4 * 64) * 4;

    cudaFuncSetAttribute((const void*)kA,
                         cudaFuncAttributeMaxDynamicSharedMemorySize, SMEM_A);
    cudaFuncSetAttribute((const void*)kB,
                         cudaFuncAttributeMaxDynamicSharedMemorySize, SMEM_KEY);

    dim3 gA(6, 1025);
    kA<<<gA, 256, SMEM_A>>>(x, wmk, wih, bih);
    kB<<<CSIZE, 256, SMEM_KEY>>>(whh, bhh);
    kC<<<32 * CSIZE, 256>>>(whh, bhh, out);
}

// round 7
// speedup vs baseline: 1.0585x; 1.0585x over previous
#include <cuda_runtime.h>
#include <cstdint>

// ---------------------------------------------------------------------------
// KeyedGRU  (B=64, T=2048, I=H=256, KB=4, KL=16)  -- all fp32
// A: gi GEMM, 128x128 tile, FFMA2, R3 tile layout (4 LDS + dup MOVs = balanced
//    LSU/FMA), double-buffered SMEM (one sync per stage).
// B: 16-step key GRU scan, one 4-CTA cluster (validated).
// C: 2048-step main GRU scan, 32 clusters x 4 CTAs, 512 threads/CTA,
//    k-half split -> wp[3][16] (96 regs, no spill), local SMEM combine,
//    st.async + mbarrier complete_tx, arm-(t+2)-after-wait (1 less sync).
// ---------------------------------------------------------------------------

#define T_STEPS 2048
#define BATCH   64
#define HID     256
#define ROWS_MAIN (T_STEPS * BATCH)
#define ROWS_ALL  (ROWS_MAIN + 64)
#define CSIZE 4
#define RPC   192
#define WS    260

__device__ float g_gi[(size_t)ROWS_ALL * 768];
__device__ float g_gates[16 * HID];

typedef unsigned long long ull;

// ---------------- helpers ----------------
__device__ __forceinline__ uint32_t smem_u32(const void* p) {
    uint32_t a;
    asm("{ .reg .u64 t; cvta.to.shared.u64 t, %1; cvt.u32.u64 %0, t; }"
        : "=r"(a) : "l"(p));
    return a;
}
__device__ __forceinline__ void st_cluster_f32(uint32_t laddr, uint32_t rank, float v) {
    uint32_t ra;
    asm volatile("mapa.shared::cluster.u32 %0, %1, %2;" : "=r"(ra) : "r"(laddr), "r"(rank));
    asm volatile("st.shared::cluster.f32 [%0], %1;" :: "r"(ra), "f"(v) : "memory");
}
__device__ __forceinline__ uint32_t mapa_addr(uint32_t laddr, uint32_t rank) {
    uint32_t ra;
    asm("mapa.shared::cluster.u32 %0, %1, %2;" : "=r"(ra) : "r"(laddr), "r"(rank));
    return ra;
}
__device__ __forceinline__ void st_async_2f(uint32_t ra, float a, float b, uint32_t rbar) {
    asm volatile("{ .reg .b64 d; mov.b64 d, {%1, %2};\n\t"
                 "st.async.shared::cluster.mbarrier::complete_tx::bytes.b64 [%0], d, [%3]; }"
                 :: "r"(ra), "f"(a), "f"(b), "r"(rbar) : "memory");
}
__device__ __forceinline__ void mbar_init(uint32_t a, uint32_t cnt) {
    asm volatile("mbarrier.init.shared.b64 [%0], %1;" :: "r"(a), "r"(cnt) : "memory");
}
__device__ __forceinline__ void mbar_arrive_expect(uint32_t a, uint32_t tx) {
    asm volatile("mbarrier.arrive.expect_tx.shared.b64 _, [%0], %1;"
                 :: "r"(a), "r"(tx) : "memory");
}
__device__ __forceinline__ void mbar_wait_parity(uint32_t mbar, uint32_t parity) {
    uint32_t done;
    asm volatile("{\n\t.reg .pred p;\n\t"
                 "mbarrier.try_wait.parity.acquire.cluster.shared::cta.b64 p, [%1], %2;\n\t"
                 "selp.b32 %0, 1, 0, p;\n\t}"
                 : "=r"(done) : "r"(mbar), "r"(parity) : "memory");
    if (!done) {
        asm volatile("{\n\t.reg .pred P1;\n\t"
                     "WAIT_LOOP_%=:\n\t"
                     "mbarrier.try_wait.parity.acquire.cluster.shared::cta.b64 P1, [%0], %1, 0x989680;\n\t"
                     "@P1 bra.uni WAIT_DONE_%=;\n\t"
                     "bra.uni WAIT_LOOP_%=;\n\t"
                     "WAIT_DONE_%=:\n\t}"
                     :: "r"(mbar), "r"(parity) : "memory");
    }
}
__device__ __forceinline__ void cluster_sync_() {
    asm volatile("barrier.cluster.arrive.aligned;" ::: "memory");
    asm volatile("barrier.cluster.wait.aligned;" ::: "memory");
}
__device__ __forceinline__ uint32_t ctarank() {
    uint32_t r; asm("mov.u32 %0, %%cluster_ctarank;" : "=r"(r)); return r;
}
__device__ __forceinline__ ull dup2(float a) {
    ull d; asm("mov.b64 %0, {%1, %1};" : "=l"(d) : "f"(a)); return d;
}
__device__ __forceinline__ void fma2(ull& c, ull a, ull b) {
    asm("fma.rn.f32x2 %0, %1, %2, %0;" : "+l"(c) : "l"(a), "l"(b));
}
__device__ __forceinline__ void unpk(ull v, float& x, float& y) {
    asm("mov.b64 {%0, %1}, %2;" : "=f"(x), "=f"(y) : "l"(v));
}
__device__ __forceinline__ float sigm_(float x)  { return 1.0f / (1.0f + __expf(-x)); }
__device__ __forceinline__ float tanh_(float x)  { return 1.0f - __fdividef(2.0f, __expf(2.0f * x) + 1.0f); }
__device__ __forceinline__ float sigmoidf_(float x) { return 1.0f / (1.0f + expf(-x)); }

// ---------------------------------------------------------------------------
// Kernel A: 128x128 tile, R3 layout (As/Bs [k][m], 4 LDS + 8 dup2 per k),
// double-buffered. grid (6, 1025), block 256, dyn smem 66KB, 2 CTAs/SM.
// ---------------------------------------------------------------------------
#define BR2 132

__global__ void __launch_bounds__(256, 2) kA(const float* __restrict__ x,
                                             const float* __restrict__ wmk,
                                             const float* __restrict__ wih,
                                             const float* __restrict__ bih)
{
    extern __shared__ __align__(16) float smA[];
    float (*As)[32][BR2] = (float (*)[32][BR2])smA;                   // [2][32][132]
    float (*Bs)[32][BR2] = (float (*)[32][BR2])(smA + 2 * 32 * BR2);  // [2][32][132]

    const int tid = threadIdx.x;
    const int nt = blockIdx.x;       // 0..5
    const int rt = blockIdx.y;       // 0..1024
    const int tx = tid & 15, ty = tid >> 4;
    const int m_base = rt * 128, n_base = nt * 128;

    ull acc[8][4];
    #pragma unroll
    for (int i = 0; i < 8; ++i)
        #pragma unroll
        for (int j = 0; j < 4; ++j) acc[i][j] = 0ull;

    float4 ra[4], rb[4];

    auto load_regs = [&](int kc) {
        const int kb = kc * 32;
        #pragma unroll
        for (int q = 0; q < 4; ++q) {
            int v = tid + q * 256;
            int m = v >> 3;
            int k4 = (v & 7) << 2;
            int row = m_base + m;
            if (row < ROWS_MAIN) {
                int t = row >> 6, b = row & 63;
                ra[q] = *(const float4*)&x[((size_t)b * T_STEPS + t) * 256 + kb + k4];
            } else if (row < ROWS_ALL) {
                int r2 = row - ROWS_MAIN;
                int l = r2 >> 2, kbk = r2 & 3;
                ra[q] = *(const float4*)&wmk[((size_t)kbk * 16 + l) * 256 + kb + k4];
            } else {
                ra[q] = make_float4(0.f, 0.f, 0.f, 0.f);
            }
            rb[q] = *(const float4*)&wih[(size_t)(n_base + m) * 256 + kb + k4];
        }
    };

    auto store_stage = [&](int buf) {
        #pragma unroll
        for (int q = 0; q < 4; ++q) {
            int v = tid + q * 256;
            int m = v >> 3;
            int k4 = (v & 7) << 2;
            const float* av = &ra[q].x;
            const float* bv = &rb[q].x;
            #pragma unroll
            for (int j = 0; j < 4; ++j) {
                As[buf][k4 + j][m] = av[j];
                Bs[buf][k4 + j][m] = bv[j];
            }
        }
    };

    load_regs(0);
    store_stage(0);
    __syncthreads();

    for (int kc = 0; kc < 8; ++kc) {
        if (kc < 7) load_regs(kc + 1);
        const int buf = kc & 1;
        #pragma unroll 8
        for (int k = 0; k < 32; ++k) {
            float4 a0 = *(const float4*)&As[buf][k][ty * 8 + 0];
            float4 a1 = *(const float4*)&As[buf][k][ty * 8 + 4];
            ulonglong2 b0 = *(const ulonglong2*)&Bs[buf][k][tx * 4];
            ulonglong2 b1 = *(const ulonglong2*)&Bs[buf][k][64 + tx * 4];
            ull ad[8];
            ad[0] = dup2(a0.x); ad[1] = dup2(a0.y); ad[2] = dup2(a0.z); ad[3] = dup2(a0.w);
            ad[4] = dup2(a1.x); ad[5] = dup2(a1.y); ad[6] = dup2(a1.z); ad[7] = dup2(a1.w);
            #pragma unroll
            for (int i = 0; i < 8; ++i) {
                fma2(acc[i][0], ad[i], b0.x);
                fma2(acc[i][1], ad[i], b0.y);
                fma2(acc[i][2], ad[i], b1.x);
                fma2(acc[i][3], ad[i], b1.y);
            }
        }
        if (kc < 7) {
            store_stage((kc + 1) & 1);
            __syncthreads();
        }
    }

    float4 bs0 = *(const float4*)&bih[n_base + tx * 4];
    float4 bs1 = *(const float4*)&bih[n_base + 64 + tx * 4];
    #pragma unroll
    for (int i = 0; i < 8; ++i) {
        int row = m_base + ty * 8 + i;
        if (row >= ROWS_ALL) break;
        float f0, f1, f2, f3;
        unpk(acc[i][0], f0, f1); unpk(acc[i][1], f2, f3);
        float4 o0 = make_float4(f0 + bs0.x, f1 + bs0.y, f2 + bs0.z, f3 + bs0.w);
        *(float4*)&g_gi[(size_t)row * 768 + n_base + tx * 4] = o0;
        unpk(acc[i][2], f0, f1); unpk(acc[i][3], f2, f3);
        float4 o1 = make_float4(f0 + bs1.x, f1 + bs1.y, f2 + bs1.z, f3 + bs1.w);
        *(float4*)&g_gi[(size_t)row * 768 + n_base + 64 + tx * 4] = o1;
    }
}

// ---------------------------------------------------------------------------
// Kernel B: key scan (16 steps, KB=4) -- unchanged (validated, ~25us).
// ---------------------------------------------------------------------------
__global__ void __launch_bounds__(256, 1) __cluster_dims__(CSIZE, 1, 1)
kB(const float* __restrict__ whh, const float* __restrict__ bhh)
{
    extern __shared__ __align__(16) float sm[];
    float* ws   = sm;
    float* hsh  = ws + RPC * WS;
    float* ghx  = hsh + 4 * HID;
    float* rbuf = ghx + 3 * 4 * 64;

    const int tid = threadIdx.x;
    const uint32_t rank = ctarank();

    for (int i = tid; i < RPC * 64; i += 256) {
        int r = i >> 6;
        int k4 = (i & 63) << 2;
        *(float4*)&ws[r * WS + k4] =
            *(const float4*)&whh[((size_t)(rank * RPC + r)) * 256 + k4];
    }
    for (int i = tid; i < 4 * HID; i += 256) hsh[i] = 0.0f;

    const uint32_t hsh_a = smem_u32(hsh);
    const uint32_t ghx_a = smem_u32(ghx);
    cluster_sync_();

    const int hl = tid & 63;
    const int bb = tid >> 6;
    const int hg = (int)rank * 64 + hl;

    for (int t = 0; t < 16; ++t) {
        float ir, ii, inn;
        {
            size_t row = (size_t)(ROWS_MAIN + t * 4 + bb);
            const float* gp = &g_gi[row * 768];
            ir = gp[hg]; ii = gp[256 + hg]; inn = gp[512 + hg];
        }
        if (tid < RPC) {
            const int rg = (int)rank * RPC + tid;
            float acc[4];
            const float bv = bhh[rg];
            #pragma unroll
            for (int b = 0; b < 4; ++b) acc[b] = bv;
            const float* wr = &ws[tid * WS];
            #pragma unroll 4
            for (int k = 0; k < 256; k += 4) {
                float4 w = *(const float4*)&wr[k];
                #pragma unroll
                for (int b = 0; b < 4; ++b) {
                    float4 h4 = *(const float4*)&hsh[b * HID + k];
                    acc[b] += w.x * h4.x + w.y * h4.y + w.z * h4.z + w.w * h4.w;
                }
            }
            const int chunk = rg >> 8;
            const int hv = rg & 255;
            const uint32_t owner = (uint32_t)(hv >> 6);
            const int hvl = hv & 63;
            #pragma unroll
            for (int b = 0; b < 4; ++b) {
                uint32_t addr = ghx_a + (uint32_t)(((chunk * 4 + b) * 64 + hvl) * 4);
                st_cluster_f32(addr, owner, acc[b]);
            }
        }
        cluster_sync_();
        {
            float hr = ghx[(0 * 4 + bb) * 64 + hl];
            float hi = ghx[(1 * 4 + bb) * 64 + hl];
            float hn = ghx[(2 * 4 + bb) * 64 + hl];
            float r = sigmoidf_(ir + hr);
            float z = sigmoidf_(ii + hi);
            float n = tanhf(inn + r * hn);
            float hold = hsh[bb * HID + hg];
            float hy = n + z * (hold - n);
            rbuf[bb * 64 + hl] = r;
            uint32_t addr = hsh_a + (uint32_t)((bb * HID + hg) * 4);
            #pragma unroll
            for (uint32_t rk = 0; rk < CSIZE; ++rk)
                st_cluster_f32(addr, rk, hy);
        }
        __syncthreads();
        if (tid < 64) {
            float s = 0.f;
            #pragma unroll
            for (int b = 0; b < 4; ++b) s += rbuf[b * 64 + tid];
            g_gates[t * 256 + (int)rank * 64 + tid] = s * 0.25f;
        }
        cluster_sync_();
    }
}

// ---------------------------------------------------------------------------
// Kernel C: main scan, 512 threads, k-half split.
// thread: kh = tid>>8 (k-half), hx = tid&255 (gate h-index).
// wp[3][16] = 96 regs. kh=1 stores 6 partials to SMEM; kh=0 combines + ships.
// Barrier arming: after wait(t), arm barrier (t&1) for step t+2 (both
// barriers pre-armed for t=0,1). One combine-sync + one tail-sync per step.
// ---------------------------------------------------------------------------
#define TXB 6144u   // 4 src * 3 gates * 64 hl * 2 b * 4B

__global__ void __launch_bounds__(512, 1) __cluster_dims__(CSIZE, 1, 1)
kC(const float* __restrict__ whh, const float* __restrict__ bhh,
   float* __restrict__ out)
{
    __shared__ __align__(16) float part[2][4][3][64][2];   // 12 KB
    __shared__ __align__(16) float hp[2][64];
    __shared__ __align__(16) float red[256][10];           // combine buffer
    __shared__ __align__(8) unsigned long long mbar[2];

    const int tid = threadIdx.x;
    const uint32_t rank = ctarank();
    const int cl = blockIdx.x >> 2;
    const int kh = tid >> 8;       // 0/1: k-half
    const int hx = tid & 255;      // gate h-index
    const int hoff = kh * 32;

    // weights: rows {hx, 256+hx, 512+hx}, k-slice rank*64 + kh*32 + [0,32)
    ull wp[3][16];
    {
        const float* wb = whh + (size_t)rank * 64 + hoff;
        #pragma unroll
        for (int j = 0; j < 3; ++j) {
            const float* wr = wb + (size_t)(j * 256 + hx) * 256;
            #pragma unroll
            for (int kk = 0; kk < 32; kk += 4) {
                ulonglong2 v = *(const ulonglong2*)&wr[kk];
                wp[j][kk / 2] = v.x;
                wp[j][kk / 2 + 1] = v.y;
            }
        }
    }

    if (tid < 128) hp[tid >> 6][tid & 63] = 0.0f;

    const uint32_t mb_a = smem_u32(&mbar[0]);
    if (tid == 0) {
        mbar_init(mb_a, 1);
        mbar_init(mb_a + 8, 1);
        mbar_arrive_expect(mb_a, TXB);       // arm t=0
        mbar_arrive_expect(mb_a + 8, TXB);   // arm t=1
    }

    // ship targets (used by kh=0 threads; hx = tid for those)
    const uint32_t owner = (uint32_t)(hx >> 6);
    const int hvl = hx & 63;
    const uint32_t part_a = smem_u32(&part[0][0][0][0][0]);
    const uint32_t ra_base = mapa_addr(part_a + (uint32_t)((rank * 384 + hvl * 2) * 4), owner);
    const uint32_t rbar_base = mapa_addr(mb_a, owner);

    const int e_b = tid >> 6;       // valid for tid<128
    const int e_hl = tid & 63;
    const int e_hg = (int)rank * 64 + e_hl;
    float bh_r = 0.f, bh_i = 0.f, bh_n = 0.f;
    if (tid < 128) {
        bh_r = bhh[e_hg];
        bh_i = bhh[256 + e_hg];
        bh_n = bhh[512 + e_hg];
    }
    const int b_glob = cl * 2 + e_b;

    cluster_sync_();   // barriers armed, hp zeroed, everywhere

    for (int t = 0; t < T_STEPS; ++t) {
        // prefetch gi + gate (tid<128)
        float ir = 0.f, ii = 0.f, inn = 0.f, gg = 1.f;
        if (tid < 128) {
            const float* gp = &g_gi[((size_t)t * BATCH + b_glob) * 768];
            ir  = gp[e_hg];
            ii  = gp[256 + e_hg];
            inn = gp[512 + e_hg];
            if (t < 16) gg = g_gates[t * 256 + e_hg];
        }

        // partial gh over this thread's k-half (32 elements)
        ull a00 = 0, a01 = 0, a10 = 0, a11 = 0, a20 = 0, a21 = 0;
        #pragma unroll
        for (int kk = 0; kk < 32; kk += 4) {
            ulonglong2 h0 = *(const ulonglong2*)&hp[0][hoff + kk];
            ulonglong2 h1 = *(const ulonglong2*)&hp[1][hoff + kk];
            ull w0a = wp[0][kk / 2], w0b = wp[0][kk / 2 + 1];
            ull w1a = wp[1][kk / 2], w1b = wp[1][kk / 2 + 1];
            ull w2a = wp[2][kk / 2], w2b = wp[2][kk / 2 + 1];
            fma2(a00, w0a, h0.x); fma2(a00, w0b, h0.y);
            fma2(a01, w0a, h1.x); fma2(a01, w0b, h1.y);
            fma2(a10, w1a, h0.x); fma2(a10, w1b, h0.y);
            fma2(a11, w1a, h1.x); fma2(a11, w1b, h1.y);
            fma2(a20, w2a, h0.x); fma2(a20, w2b, h0.y);
            fma2(a21, w2a, h1.x); fma2(a21, w2b, h1.y);
        }
        // pair-reduce: s[g][b]
        float s00, s01, s10, s11, s20, s21;
        {
            float x0, y0;
            unpk(a00, x0, y0); s00 = x0 + y0;
            unpk(a01, x0, y0); s01 = x0 + y0;
            unpk(a10, x0, y0); s10 = x0 + y0;
            unpk(a11, x0, y0); s11 = x0 + y0;
            unpk(a20, x0, y0); s20 = x0 + y0;
            unpk(a21, x0, y0); s21 = x0 + y0;
        }

        if (kh == 1) {
            *(float2*)&red[hx][0] = make_float2(s00, s01);
            *(float2*)&red[hx][2] = make_float2(s10, s11);
            *(float2*)&red[hx][4] = make_float2(s20, s21);
        }
        __syncthreads();

        if (kh == 0) {
            const uint32_t pbase = ra_base + (uint32_t)((t & 1) * 6144);
            const uint32_t rb = rbar_base + 8u * (uint32_t)(t & 1);
            float2 o0 = *(const float2*)&red[hx][0];
            float2 o1 = *(const float2*)&red[hx][2];
            float2 o2 = *(const float2*)&red[hx][4];
            st_async_2f(pbase + 0 * 512, s00 + o0.x, s01 + o0.y, rb);
            st_async_2f(pbase + 1 * 512, s10 + o1.x, s11 + o1.y, rb);
            st_async_2f(pbase + 2 * 512, s20 + o2.x, s21 + o2.y, rb);
        }

        // wait for all 4 CTAs' partials (cluster-scope acquire)
        mbar_wait_parity(mb_a + 8u * (t & 1), (uint32_t)((t >> 1) & 1));

        // re-arm this barrier for step t+2 (safe: phase t just completed;
        // any ship targeting the new phase is gated by our post-epilogue
        // tail syncs of steps t and t+1)
        if (tid == 0)
            mbar_arrive_expect(mb_a + 8u * (t & 1), TXB);

        // epilogue
        if (tid < 128) {
            const int p = t & 1;
            float s_r = bh_r, s_i = bh_i, s_n = bh_n;
            #pragma unroll
            for (int src = 0; src < 4; ++src) {
                s_r += part[p][src][0][e_hl][e_b];
                s_i += part[p][src][1][e_hl][e_b];
                s_n += part[p][src][2][e_hl][e_b];
            }
            float r = sigm_(ir + s_r);
            float z = sigm_(ii + s_i);
            float n = tanh_(inn + r * s_n);
            float hold = hp[e_b][e_hl];
            float hy = n + z * (hold - n);
            out[((size_t)t * BATCH + b_glob) * HID + e_hg] = hy;
            hp[e_b][e_hl] = hy * gg;
        }
        __syncthreads();
    }
}

// ---------------------------------------------------------------------------
extern "C" void kernel_launch(void* const* d_in, const int* in_sizes, int n_in,
                              void* d_out, int out_size)
{
    const float* x   = (const float*)d_in[0];
    const float* wmk = (const float*)d_in[1];
    const float* wih = (const float*)d_in[2];
    const float* whh = (const float*)d_in[3];
    const float* bih = (const float*)d_in[4];
    const float* bhh = (const float*)d_in[5];
    float* out = (float*)d_out;

    constexpr int SMEM_A   = 2 * 2 * 32 * BR2 * 4;   // 67,584 B
    constexpr int SMEM_KEY = (RPC * WS + 4 * HID + 3 * 4 * 64 + 4 * 64) * 4;

    cudaFuncSetAttribute((const void*)kA,
                         cudaFuncAttributeMaxDynamicSharedMemorySize, SMEM_A);
    cudaFuncSetAttribute((const void*)kB,
                         cudaFuncAttributeMaxDynamicSharedMemorySize, SMEM_KEY);

    dim3 gA(6, 1025);
    kA<<<gA, 256, SMEM_A>>>(x, wmk, wih, bih);
    kB<<<CSIZE, 256, SMEM_KEY>>>(whh, bhh);
    kC<<<32 * CSIZE, 512>>>(whh, bhh, out);
}